// round 1
// baseline (speedup 1.0000x reference)
#include <cuda_runtime.h>
#include <math.h>

#define B_   2
#define S_   2048
#define DM_  2048
#define H_   16
#define DH_  128
#define BSM  (B_ * S_)   // 4096 rows

// Scratch (static device globals — no allocation allowed)
__device__ float g_q[(size_t)BSM * DM_];
__device__ float g_k[(size_t)BSM * DM_];
__device__ float g_v[(size_t)BSM * DM_];
__device__ float g_o[(size_t)BSM * DM_];

// ---------------------------------------------------------------------------
// SGEMM: C[M,N] = A[M,K] @ W[N,K]^T   (both operands K-contiguous row-major)
// 128x128 tile, BK=16, 256 threads, 8x8 per thread.
// ---------------------------------------------------------------------------
#define GBM 128
#define GBN 128
#define GBK 16
#define GAS 132   // padded stride to break bank conflicts

__global__ __launch_bounds__(256, 2)
void sgemm_nt(const float* __restrict__ A, const float* __restrict__ W,
              float* __restrict__ C, int M, int N, int K) {
    __shared__ float As[GBK][GAS];
    __shared__ float Bs[GBK][GAS];

    const int tid  = threadIdx.x;
    const int tx   = tid & 15;          // 0..15 -> N
    const int ty   = tid >> 4;          // 0..15 -> M
    const int lrow = tid >> 2;          // 0..63
    const int lcol = (tid & 3) << 2;    // 0,4,8,12

    const float* Ab = A + (size_t)blockIdx.y * GBM * K;
    const float* Wb = W + (size_t)blockIdx.x * GBN * K;

    float acc[8][8];
#pragma unroll
    for (int i = 0; i < 8; i++)
#pragma unroll
        for (int j = 0; j < 8; j++) acc[i][j] = 0.f;

    for (int k0 = 0; k0 < K; k0 += GBK) {
#pragma unroll
        for (int rr = 0; rr < 2; rr++) {
            int r = lrow + rr * 64;
            float4 va = *(const float4*)(Ab + (size_t)r * K + k0 + lcol);
            As[lcol + 0][r] = va.x; As[lcol + 1][r] = va.y;
            As[lcol + 2][r] = va.z; As[lcol + 3][r] = va.w;
            float4 vb = *(const float4*)(Wb + (size_t)r * K + k0 + lcol);
            Bs[lcol + 0][r] = vb.x; Bs[lcol + 1][r] = vb.y;
            Bs[lcol + 2][r] = vb.z; Bs[lcol + 3][r] = vb.w;
        }
        __syncthreads();

#pragma unroll
        for (int k = 0; k < GBK; k++) {
            float a[8], b[8];
            *(float4*)&a[0] = *(const float4*)&As[k][ty * 8];
            *(float4*)&a[4] = *(const float4*)&As[k][ty * 8 + 4];
            *(float4*)&b[0] = *(const float4*)&Bs[k][tx * 8];
            *(float4*)&b[4] = *(const float4*)&Bs[k][tx * 8 + 4];
#pragma unroll
            for (int i = 0; i < 8; i++)
#pragma unroll
                for (int j = 0; j < 8; j++)
                    acc[i][j] = fmaf(a[i], b[j], acc[i][j]);
        }
        __syncthreads();
    }

    float* Cb = C + (size_t)(blockIdx.y * GBM + ty * 8) * N + blockIdx.x * GBN + tx * 8;
#pragma unroll
    for (int i = 0; i < 8; i++) {
        *(float4*)(Cb + (size_t)i * N)     = make_float4(acc[i][0], acc[i][1], acc[i][2], acc[i][3]);
        *(float4*)(Cb + (size_t)i * N + 4) = make_float4(acc[i][4], acc[i][5], acc[i][6], acc[i][7]);
    }
}

// ---------------------------------------------------------------------------
// RMSNorm (over head dim 128) + RoPE, one warp per (b,s,h) row, in-place.
// rope_emb: (S,1,64,2,2): f(s,i,p,c) at s*256 + i*4 + p*2 + c.
// out[i]     = f(s,i,0,0)*t[i] + f(s,i,0,1)*t[i+64]
// out[i+64]  = f(s,i,1,0)*t[i] + f(s,i,1,1)*t[i+64]
// ---------------------------------------------------------------------------
__global__ __launch_bounds__(256)
void norm_rope(float* __restrict__ t, const float* __restrict__ rope,
               const float* __restrict__ w) {
    int warp = (blockIdx.x * blockDim.x + threadIdx.x) >> 5;
    int lane = threadIdx.x & 31;
    if (warp >= BSM * H_) return;
    int h  = warp % H_;
    int bs = warp / H_;          // b*S + s
    int s  = bs % S_;

    float* row = t + (size_t)bs * DM_ + h * DH_;
    float v0 = row[lane], v1 = row[lane + 32], v2 = row[lane + 64], v3 = row[lane + 96];
    float ss = v0 * v0 + v1 * v1 + v2 * v2 + v3 * v3;
#pragma unroll
    for (int o = 16; o; o >>= 1) ss += __shfl_xor_sync(0xFFFFFFFFu, ss, o);
    float inv = rsqrtf(ss * (1.0f / 128.0f) + 1e-6f);
    v0 *= inv * w[lane];      v1 *= inv * w[lane + 32];
    v2 *= inv * w[lane + 64]; v3 *= inv * w[lane + 96];

    const float* f = rope + (size_t)s * 256;
    // pair (i=lane, i+64)
    float f00 = f[lane * 4 + 0], f01 = f[lane * 4 + 1];
    float f10 = f[lane * 4 + 2], f11 = f[lane * 4 + 3];
    float y0 = f00 * v0 + f01 * v2;
    float y2 = f10 * v0 + f11 * v2;
    // pair (i=lane+32, i+96)
    int i2 = lane + 32;
    float g00 = f[i2 * 4 + 0], g01 = f[i2 * 4 + 1];
    float g10 = f[i2 * 4 + 2], g11 = f[i2 * 4 + 3];
    float y1 = g00 * v1 + g01 * v3;
    float y3 = g10 * v1 + g11 * v3;

    row[lane] = y0; row[lane + 32] = y1; row[lane + 64] = y2; row[lane + 96] = y3;
}

// ---------------------------------------------------------------------------
// Flash attention: per (b, h, q-tile of 64). 512 threads, BKV = 64.
// K stored transposed in smem (Kt[d][key]) so the score micro-GEMM reads are
// conflict-free; online softmax in smem; PV with per-thread 16-wide O slice.
// ---------------------------------------------------------------------------
#define FT   512
#define FBQ  64
#define FBK  64
#define QSTR 132
#define KTS  68
#define VSTR 132
#define SSTR 68
#define FLASH_SMEM ((FBQ*QSTR + DH_*KTS + FBK*VSTR + FBQ*SSTR + 3*FBQ) * sizeof(float))

__global__ __launch_bounds__(FT, 1)
void flash_kernel(const float* __restrict__ Q, const float* __restrict__ Kg,
                  const float* __restrict__ Vg, float* __restrict__ O) {
    extern __shared__ float sm[];
    float* Qs   = sm;                       // [64][132]
    float* Kt   = Qs + FBQ * QSTR;          // [128][68]
    float* Vs   = Kt + DH_ * KTS;           // [64][132]
    float* Ssm  = Vs + FBK * VSTR;          // [64][68]
    float* m_s  = Ssm + FBQ * SSTR;
    float* l_s  = m_s + FBQ;
    float* al_s = l_s + FBQ;

    const int tid = threadIdx.x;
    const int q0  = blockIdx.x * FBQ;
    const int h   = blockIdx.y;
    const int b   = blockIdx.z;
    const size_t headoff = (size_t)h * DH_;
    const size_t rowbase = (size_t)b * S_;

    const int lr = tid & 63;     // row within tile (load + PV mapping)
    const int lc = tid >> 6;     // 0..7  -> dims lc*16 .. lc*16+15

    // Load Q tile, pre-scaled by 1/sqrt(DH)
    {
        const float scale = 0.08838834764831845f;
        const float* qrow = Q + (rowbase + q0 + lr) * (size_t)DM_ + headoff + lc * 16;
        float* qd = Qs + lr * QSTR + lc * 16;
#pragma unroll
        for (int i = 0; i < 4; i++) {
            float4 v = *(const float4*)(qrow + i * 4);
            *(float4*)(qd + i * 4) = make_float4(v.x * scale, v.y * scale, v.z * scale, v.w * scale);
        }
    }
    if (tid < FBQ) { m_s[tid] = -1e30f; l_s[tid] = 0.f; }

    float Oacc[16];
#pragma unroll
    for (int i = 0; i < 16; i++) Oacc[i] = 0.f;

    const int sty = tid >> 4;   // 0..31 -> score rows sty*2, sty*2+1
    const int stx = tid & 15;   // 0..15 -> score cols stx*4 .. +3

    for (int j0 = 0; j0 < S_; j0 += FBK) {
        // Load K (transposed) and V tiles
        {
            const float* krow = Kg + (rowbase + j0 + lr) * (size_t)DM_ + headoff + lc * 16;
#pragma unroll
            for (int i = 0; i < 4; i++) {
                float4 v = *(const float4*)(krow + i * 4);
                int d = lc * 16 + i * 4;
                Kt[(d + 0) * KTS + lr] = v.x;
                Kt[(d + 1) * KTS + lr] = v.y;
                Kt[(d + 2) * KTS + lr] = v.z;
                Kt[(d + 3) * KTS + lr] = v.w;
            }
            const float* vrow = Vg + (rowbase + j0 + lr) * (size_t)DM_ + headoff + lc * 16;
            float* vd = Vs + lr * VSTR + lc * 16;
#pragma unroll
            for (int i = 0; i < 4; i++)
                *(float4*)(vd + i * 4) = *(const float4*)(vrow + i * 4);
        }
        __syncthreads();

        // Scores: S = Q K^T (2x4 tile per thread)
        {
            float a00 = 0.f, a01 = 0.f, a02 = 0.f, a03 = 0.f;
            float a10 = 0.f, a11 = 0.f, a12 = 0.f, a13 = 0.f;
            const float* q0p = Qs + (sty * 2) * QSTR;
            const float* q1p = q0p + QSTR;
#pragma unroll 8
            for (int d = 0; d < DH_; d++) {
                float4 kv = *(const float4*)&Kt[d * KTS + stx * 4];
                float qa = q0p[d], qb = q1p[d];
                a00 = fmaf(qa, kv.x, a00); a01 = fmaf(qa, kv.y, a01);
                a02 = fmaf(qa, kv.z, a02); a03 = fmaf(qa, kv.w, a03);
                a10 = fmaf(qb, kv.x, a10); a11 = fmaf(qb, kv.y, a11);
                a12 = fmaf(qb, kv.z, a12); a13 = fmaf(qb, kv.w, a13);
            }
            float* s0 = Ssm + (sty * 2) * SSTR + stx * 4;
            *(float4*)s0          = make_float4(a00, a01, a02, a03);
            *(float4*)(s0 + SSTR) = make_float4(a10, a11, a12, a13);
        }
        __syncthreads();

        // Online softmax per row (one thread per row)
        if (tid < FBQ) {
            float* srow = Ssm + tid * SSTR;
            float mold = m_s[tid];
            float mx = mold;
#pragma unroll
            for (int kk = 0; kk < 16; kk++) {
                float4 v = *(const float4*)(srow + kk * 4);
                mx = fmaxf(mx, fmaxf(fmaxf(v.x, v.y), fmaxf(v.z, v.w)));
            }
            float alpha = __expf(mold - mx);
            float lsum = 0.f;
#pragma unroll
            for (int kk = 0; kk < 16; kk++) {
                float4 v = *(const float4*)(srow + kk * 4);
                float4 p;
                p.x = __expf(v.x - mx); p.y = __expf(v.y - mx);
                p.z = __expf(v.z - mx); p.w = __expf(v.w - mx);
                lsum += (p.x + p.y) + (p.z + p.w);
                *(float4*)(srow + kk * 4) = p;
            }
            m_s[tid]  = mx;
            l_s[tid]  = l_s[tid] * alpha + lsum;
            al_s[tid] = alpha;
        }
        __syncthreads();

        // O = O*alpha + P @ V  (each thread: row lr, dims lc*16..+15)
        {
            float al = al_s[lr];
#pragma unroll
            for (int i = 0; i < 16; i++) Oacc[i] *= al;
            const float* srow = Ssm + lr * SSTR;
#pragma unroll 2
            for (int k4 = 0; k4 < FBK; k4 += 4) {
                float4 s4 = *(const float4*)(srow + k4);
                float sarr[4] = { s4.x, s4.y, s4.z, s4.w };
                const float* vp = Vs + k4 * VSTR + lc * 16;
#pragma unroll
                for (int kk = 0; kk < 4; kk++) {
                    float sv = sarr[kk];
                    const float* v = vp + kk * VSTR;
#pragma unroll
                    for (int i = 0; i < 4; i++) {
                        float4 vv = *(const float4*)(v + i * 4);
                        Oacc[i * 4 + 0] = fmaf(sv, vv.x, Oacc[i * 4 + 0]);
                        Oacc[i * 4 + 1] = fmaf(sv, vv.y, Oacc[i * 4 + 1]);
                        Oacc[i * 4 + 2] = fmaf(sv, vv.z, Oacc[i * 4 + 2]);
                        Oacc[i * 4 + 3] = fmaf(sv, vv.w, Oacc[i * 4 + 3]);
                    }
                }
            }
        }
        __syncthreads();  // before next tile overwrites Kt/Vs/Ssm
    }

    // Epilogue: normalize and store
    float linv = 1.0f / l_s[lr];
    float* orow = O + (rowbase + q0 + lr) * (size_t)DM_ + headoff + lc * 16;
#pragma unroll
    for (int i = 0; i < 4; i++)
        *(float4*)(orow + i * 4) = make_float4(Oacc[i * 4 + 0] * linv, Oacc[i * 4 + 1] * linv,
                                               Oacc[i * 4 + 2] * linv, Oacc[i * 4 + 3] * linv);
}

// ---------------------------------------------------------------------------
extern "C" void kernel_launch(void* const* d_in, const int* in_sizes, int n_in,
                              void* d_out, int out_size) {
    const float* x    = (const float*)d_in[0];
    const float* rope = (const float*)d_in[1];
    const float* wq   = (const float*)d_in[2];
    const float* wk   = (const float*)d_in[3];
    const float* wv   = (const float*)d_in[4];
    const float* wo   = (const float*)d_in[5];
    const float* qnw  = (const float*)d_in[6];
    const float* knw  = (const float*)d_in[7];
    float* out = (float*)d_out;

    float *q, *k, *v, *o;
    cudaGetSymbolAddress((void**)&q, g_q);
    cudaGetSymbolAddress((void**)&k, g_k);
    cudaGetSymbolAddress((void**)&v, g_v);
    cudaGetSymbolAddress((void**)&o, g_o);

    dim3 ggrid(DM_ / GBN, BSM / GBM);   // (16, 32)

    sgemm_nt<<<ggrid, 256>>>(x, wq, q, BSM, DM_, DM_);
    sgemm_nt<<<ggrid, 256>>>(x, wk, k, BSM, DM_, DM_);
    sgemm_nt<<<ggrid, 256>>>(x, wv, v, BSM, DM_, DM_);

    int nwarps = BSM * H_;              // 65536 rows
    norm_rope<<<nwarps / 8, 256>>>(q, rope, qnw);
    norm_rope<<<nwarps / 8, 256>>>(k, rope, knw);

    static int smem_set = 0;
    if (!smem_set) {
        cudaFuncSetAttribute(flash_kernel, cudaFuncAttributeMaxDynamicSharedMemorySize,
                             (int)FLASH_SMEM);
        smem_set = 1;
    }
    flash_kernel<<<dim3(S_ / FBQ, H_, B_), FT, FLASH_SMEM>>>(q, k, v, o);

    sgemm_nt<<<ggrid, 256>>>(o, wo, out, BSM, DM_, DM_);
}

// round 2
// speedup vs baseline: 1.4937x; 1.4937x over previous
#include <cuda_runtime.h>
#include <math.h>
#include <stdint.h>

#define B_   2
#define S_   2048
#define DM_  2048
#define H_   16
#define DH_  128
#define BSM  (B_ * S_)   // 4096 rows

// Scratch (static device globals — no allocation allowed)
__device__ float g_q[(size_t)BSM * DM_];
__device__ float g_k[(size_t)BSM * DM_];
__device__ float g_v[(size_t)BSM * DM_];
__device__ float g_o[(size_t)BSM * DM_];

// ---------------------------------------------------------------------------
// TF32 tensor-core GEMM: C[M,N] = A[M,K] @ W[N,K]^T  (K-contiguous row-major)
// Block 128x128x32, 8 warps, warp tile 32x64 (2x8 m16n8k8 per k-step).
// Smem m-major, stride 36 words (conflict-free STS.128 fill + fragment LDS).
// ---------------------------------------------------------------------------
#define TBM 128
#define TBN 128
#define TBK 32
#define TST 36   // smem row stride in words

__device__ __forceinline__ float to_tf32(float x) {
    float r;
    asm("cvt.rna.tf32.f32 %0, %1;" : "=f"(r) : "f"(x));
    return r;
}

__device__ __forceinline__ void mma_tf32(float* c, const uint32_t* a, const uint32_t* b) {
    asm volatile(
        "mma.sync.aligned.m16n8k8.row.col.f32.tf32.tf32.f32 "
        "{%0,%1,%2,%3}, {%4,%5,%6,%7}, {%8,%9}, {%0,%1,%2,%3};"
        : "+f"(c[0]), "+f"(c[1]), "+f"(c[2]), "+f"(c[3])
        : "r"(a[0]), "r"(a[1]), "r"(a[2]), "r"(a[3]), "r"(b[0]), "r"(b[1]));
}

__global__ __launch_bounds__(256)
void tf32_gemm_nt(const float* __restrict__ A, const float* __restrict__ W,
                  float* __restrict__ C, int M, int N, int K) {
    __shared__ float As[TBM][TST];   // [m][k]
    __shared__ float Bs[TBN][TST];   // [n][k]

    const int tid  = threadIdx.x;
    const int lane = tid & 31;
    const int w    = tid >> 5;       // 0..7
    const int wm   = w & 3;          // 4 warps in M
    const int wn   = w >> 2;         // 2 warps in N
    const int g    = lane >> 2;      // 0..7
    const int tg   = lane & 3;       // 0..3

    const int lr = tid >> 3;         // 0..31 (load row base)
    const int kc = (tid & 7) * 4;    // 0,4,...,28 (load k offset)

    const float* Ab = A + (size_t)blockIdx.y * TBM * K;
    const float* Wb = W + (size_t)blockIdx.x * TBN * K;

    float acc[2][8][4];
#pragma unroll
    for (int mt = 0; mt < 2; mt++)
#pragma unroll
        for (int nt = 0; nt < 8; nt++)
#pragma unroll
            for (int i = 0; i < 4; i++) acc[mt][nt][i] = 0.f;

    float4 pa[4], pb[4];

    // prologue: load chunk 0
#pragma unroll
    for (int p = 0; p < 4; p++) {
        int r = lr + p * 32;
        pa[p] = *(const float4*)(Ab + (size_t)r * K + kc);
        pb[p] = *(const float4*)(Wb + (size_t)r * K + kc);
    }
#pragma unroll
    for (int p = 0; p < 4; p++) {
        int r = lr + p * 32;
        *(float4*)&As[r][kc] = make_float4(to_tf32(pa[p].x), to_tf32(pa[p].y),
                                           to_tf32(pa[p].z), to_tf32(pa[p].w));
        *(float4*)&Bs[r][kc] = make_float4(to_tf32(pb[p].x), to_tf32(pb[p].y),
                                           to_tf32(pb[p].z), to_tf32(pb[p].w));
    }
    __syncthreads();

    const int rb = wm * 32;   // warp M base
    const int cb = wn * 64;   // warp N base

    for (int k0 = TBK; k0 <= K; k0 += TBK) {
        const bool has_next = (k0 < K);
        if (has_next) {
#pragma unroll
            for (int p = 0; p < 4; p++) {
                int r = lr + p * 32;
                pa[p] = *(const float4*)(Ab + (size_t)r * K + k0 + kc);
                pb[p] = *(const float4*)(Wb + (size_t)r * K + k0 + kc);
            }
        }

#pragma unroll
        for (int ks = 0; ks < 4; ks++) {
            const int kb = ks * 8;
            uint32_t af[2][4], bf[8][2];
#pragma unroll
            for (int mt = 0; mt < 2; mt++) {
                int mrow = rb + mt * 16;
                af[mt][0] = __float_as_uint(As[mrow + g][kb + tg]);
                af[mt][1] = __float_as_uint(As[mrow + g + 8][kb + tg]);
                af[mt][2] = __float_as_uint(As[mrow + g][kb + tg + 4]);
                af[mt][3] = __float_as_uint(As[mrow + g + 8][kb + tg + 4]);
            }
#pragma unroll
            for (int nt = 0; nt < 8; nt++) {
                int ncol = cb + nt * 8;
                bf[nt][0] = __float_as_uint(Bs[ncol + g][kb + tg]);
                bf[nt][1] = __float_as_uint(Bs[ncol + g][kb + tg + 4]);
            }
#pragma unroll
            for (int mt = 0; mt < 2; mt++)
#pragma unroll
                for (int nt = 0; nt < 8; nt++)
                    mma_tf32(acc[mt][nt], af[mt], bf[nt]);
        }

        if (has_next) {
            __syncthreads();
#pragma unroll
            for (int p = 0; p < 4; p++) {
                int r = lr + p * 32;
                *(float4*)&As[r][kc] = make_float4(to_tf32(pa[p].x), to_tf32(pa[p].y),
                                                   to_tf32(pa[p].z), to_tf32(pa[p].w));
                *(float4*)&Bs[r][kc] = make_float4(to_tf32(pb[p].x), to_tf32(pb[p].y),
                                                   to_tf32(pb[p].z), to_tf32(pb[p].w));
            }
            __syncthreads();
        }
    }

    // epilogue: c0 (g, 2tg), c1 (g, 2tg+1), c2 (g+8, 2tg), c3 (g+8, 2tg+1)
#pragma unroll
    for (int mt = 0; mt < 2; mt++) {
#pragma unroll
        for (int nt = 0; nt < 8; nt++) {
            int row = blockIdx.y * TBM + rb + mt * 16 + g;
            int col = blockIdx.x * TBN + cb + nt * 8 + tg * 2;
            *(float2*)(C + (size_t)row * N + col) =
                make_float2(acc[mt][nt][0], acc[mt][nt][1]);
            *(float2*)(C + (size_t)(row + 8) * N + col) =
                make_float2(acc[mt][nt][2], acc[mt][nt][3]);
        }
    }
}

// ---------------------------------------------------------------------------
// RMSNorm (over head dim 128) + RoPE, one warp per (b,s,h) row, in-place.
// ---------------------------------------------------------------------------
__global__ __launch_bounds__(256)
void norm_rope(float* __restrict__ t, const float* __restrict__ rope,
               const float* __restrict__ w) {
    int warp = (blockIdx.x * blockDim.x + threadIdx.x) >> 5;
    int lane = threadIdx.x & 31;
    if (warp >= BSM * H_) return;
    int h  = warp % H_;
    int bs = warp / H_;
    int s  = bs % S_;

    float* row = t + (size_t)bs * DM_ + h * DH_;
    float v0 = row[lane], v1 = row[lane + 32], v2 = row[lane + 64], v3 = row[lane + 96];
    float ss = v0 * v0 + v1 * v1 + v2 * v2 + v3 * v3;
#pragma unroll
    for (int o = 16; o; o >>= 1) ss += __shfl_xor_sync(0xFFFFFFFFu, ss, o);
    float inv = rsqrtf(ss * (1.0f / 128.0f) + 1e-6f);
    v0 *= inv * w[lane];      v1 *= inv * w[lane + 32];
    v2 *= inv * w[lane + 64]; v3 *= inv * w[lane + 96];

    const float* f = rope + (size_t)s * 256;
    float f00 = f[lane * 4 + 0], f01 = f[lane * 4 + 1];
    float f10 = f[lane * 4 + 2], f11 = f[lane * 4 + 3];
    float y0 = f00 * v0 + f01 * v2;
    float y2 = f10 * v0 + f11 * v2;
    int i2 = lane + 32;
    float g00 = f[i2 * 4 + 0], g01 = f[i2 * 4 + 1];
    float g10 = f[i2 * 4 + 2], g11 = f[i2 * 4 + 3];
    float y1 = g00 * v1 + g01 * v3;
    float y3 = g10 * v1 + g11 * v3;

    row[lane] = y0; row[lane + 32] = y1; row[lane + 64] = y2; row[lane + 96] = y3;
}

// ---------------------------------------------------------------------------
// Flash attention (fp32): per (b, h, q-tile of 64). 512 threads, BKV = 64.
// ---------------------------------------------------------------------------
#define FT   512
#define FBQ  64
#define FBK  64
#define QSTR 132
#define KTS  68
#define VSTR 132
#define SSTR 68
#define FLASH_SMEM ((FBQ*QSTR + DH_*KTS + FBK*VSTR + FBQ*SSTR + 3*FBQ) * sizeof(float))

__global__ __launch_bounds__(FT, 1)
void flash_kernel(const float* __restrict__ Q, const float* __restrict__ Kg,
                  const float* __restrict__ Vg, float* __restrict__ O) {
    extern __shared__ float sm[];
    float* Qs   = sm;
    float* Kt   = Qs + FBQ * QSTR;
    float* Vs   = Kt + DH_ * KTS;
    float* Ssm  = Vs + FBK * VSTR;
    float* m_s  = Ssm + FBQ * SSTR;
    float* l_s  = m_s + FBQ;
    float* al_s = l_s + FBQ;

    const int tid = threadIdx.x;
    const int q0  = blockIdx.x * FBQ;
    const int h   = blockIdx.y;
    const int b   = blockIdx.z;
    const size_t headoff = (size_t)h * DH_;
    const size_t rowbase = (size_t)b * S_;

    const int lr = tid & 63;
    const int lc = tid >> 6;

    {
        const float scale = 0.08838834764831845f;
        const float* qrow = Q + (rowbase + q0 + lr) * (size_t)DM_ + headoff + lc * 16;
        float* qd = Qs + lr * QSTR + lc * 16;
#pragma unroll
        for (int i = 0; i < 4; i++) {
            float4 v = *(const float4*)(qrow + i * 4);
            *(float4*)(qd + i * 4) = make_float4(v.x * scale, v.y * scale, v.z * scale, v.w * scale);
        }
    }
    if (tid < FBQ) { m_s[tid] = -1e30f; l_s[tid] = 0.f; }

    float Oacc[16];
#pragma unroll
    for (int i = 0; i < 16; i++) Oacc[i] = 0.f;

    const int sty = tid >> 4;
    const int stx = tid & 15;

    for (int j0 = 0; j0 < S_; j0 += FBK) {
        {
            const float* krow = Kg + (rowbase + j0 + lr) * (size_t)DM_ + headoff + lc * 16;
#pragma unroll
            for (int i = 0; i < 4; i++) {
                float4 v = *(const float4*)(krow + i * 4);
                int d = lc * 16 + i * 4;
                Kt[(d + 0) * KTS + lr] = v.x;
                Kt[(d + 1) * KTS + lr] = v.y;
                Kt[(d + 2) * KTS + lr] = v.z;
                Kt[(d + 3) * KTS + lr] = v.w;
            }
            const float* vrow = Vg + (rowbase + j0 + lr) * (size_t)DM_ + headoff + lc * 16;
            float* vd = Vs + lr * VSTR + lc * 16;
#pragma unroll
            for (int i = 0; i < 4; i++)
                *(float4*)(vd + i * 4) = *(const float4*)(vrow + i * 4);
        }
        __syncthreads();

        {
            float a00 = 0.f, a01 = 0.f, a02 = 0.f, a03 = 0.f;
            float a10 = 0.f, a11 = 0.f, a12 = 0.f, a13 = 0.f;
            const float* q0p = Qs + (sty * 2) * QSTR;
            const float* q1p = q0p + QSTR;
#pragma unroll 8
            for (int d = 0; d < DH_; d++) {
                float4 kv = *(const float4*)&Kt[d * KTS + stx * 4];
                float qa = q0p[d], qb = q1p[d];
                a00 = fmaf(qa, kv.x, a00); a01 = fmaf(qa, kv.y, a01);
                a02 = fmaf(qa, kv.z, a02); a03 = fmaf(qa, kv.w, a03);
                a10 = fmaf(qb, kv.x, a10); a11 = fmaf(qb, kv.y, a11);
                a12 = fmaf(qb, kv.z, a12); a13 = fmaf(qb, kv.w, a13);
            }
            float* s0 = Ssm + (sty * 2) * SSTR + stx * 4;
            *(float4*)s0          = make_float4(a00, a01, a02, a03);
            *(float4*)(s0 + SSTR) = make_float4(a10, a11, a12, a13);
        }
        __syncthreads();

        if (tid < FBQ) {
            float* srow = Ssm + tid * SSTR;
            float mold = m_s[tid];
            float mx = mold;
#pragma unroll
            for (int kk = 0; kk < 16; kk++) {
                float4 v = *(const float4*)(srow + kk * 4);
                mx = fmaxf(mx, fmaxf(fmaxf(v.x, v.y), fmaxf(v.z, v.w)));
            }
            float alpha = __expf(mold - mx);
            float lsum = 0.f;
#pragma unroll
            for (int kk = 0; kk < 16; kk++) {
                float4 v = *(const float4*)(srow + kk * 4);
                float4 p;
                p.x = __expf(v.x - mx); p.y = __expf(v.y - mx);
                p.z = __expf(v.z - mx); p.w = __expf(v.w - mx);
                lsum += (p.x + p.y) + (p.z + p.w);
                *(float4*)(srow + kk * 4) = p;
            }
            m_s[tid]  = mx;
            l_s[tid]  = l_s[tid] * alpha + lsum;
            al_s[tid] = alpha;
        }
        __syncthreads();

        {
            float al = al_s[lr];
#pragma unroll
            for (int i = 0; i < 16; i++) Oacc[i] *= al;
            const float* srow = Ssm + lr * SSTR;
#pragma unroll 2
            for (int k4 = 0; k4 < FBK; k4 += 4) {
                float4 s4 = *(const float4*)(srow + k4);
                float sarr[4] = { s4.x, s4.y, s4.z, s4.w };
                const float* vp = Vs + k4 * VSTR + lc * 16;
#pragma unroll
                for (int kk = 0; kk < 4; kk++) {
                    float sv = sarr[kk];
                    const float* v = vp + kk * VSTR;
#pragma unroll
                    for (int i = 0; i < 4; i++) {
                        float4 vv = *(const float4*)(v + i * 4);
                        Oacc[i * 4 + 0] = fmaf(sv, vv.x, Oacc[i * 4 + 0]);
                        Oacc[i * 4 + 1] = fmaf(sv, vv.y, Oacc[i * 4 + 1]);
                        Oacc[i * 4 + 2] = fmaf(sv, vv.z, Oacc[i * 4 + 2]);
                        Oacc[i * 4 + 3] = fmaf(sv, vv.w, Oacc[i * 4 + 3]);
                    }
                }
            }
        }
        __syncthreads();
    }

    float linv = 1.0f / l_s[lr];
    float* orow = O + (rowbase + q0 + lr) * (size_t)DM_ + headoff + lc * 16;
#pragma unroll
    for (int i = 0; i < 4; i++)
        *(float4*)(orow + i * 4) = make_float4(Oacc[i * 4 + 0] * linv, Oacc[i * 4 + 1] * linv,
                                               Oacc[i * 4 + 2] * linv, Oacc[i * 4 + 3] * linv);
}

// ---------------------------------------------------------------------------
extern "C" void kernel_launch(void* const* d_in, const int* in_sizes, int n_in,
                              void* d_out, int out_size) {
    const float* x    = (const float*)d_in[0];
    const float* rope = (const float*)d_in[1];
    const float* wq   = (const float*)d_in[2];
    const float* wk   = (const float*)d_in[3];
    const float* wv   = (const float*)d_in[4];
    const float* wo   = (const float*)d_in[5];
    const float* qnw  = (const float*)d_in[6];
    const float* knw  = (const float*)d_in[7];
    float* out = (float*)d_out;

    float *q, *k, *v, *o;
    cudaGetSymbolAddress((void**)&q, g_q);
    cudaGetSymbolAddress((void**)&k, g_k);
    cudaGetSymbolAddress((void**)&v, g_v);
    cudaGetSymbolAddress((void**)&o, g_o);

    dim3 ggrid(DM_ / TBN, BSM / TBM);   // (16, 32)

    tf32_gemm_nt<<<ggrid, 256>>>(x, wq, q, BSM, DM_, DM_);
    tf32_gemm_nt<<<ggrid, 256>>>(x, wk, k, BSM, DM_, DM_);
    tf32_gemm_nt<<<ggrid, 256>>>(x, wv, v, BSM, DM_, DM_);

    int nwarps = BSM * H_;
    norm_rope<<<nwarps / 8, 256>>>(q, rope, qnw);
    norm_rope<<<nwarps / 8, 256>>>(k, rope, knw);

    static int smem_set = 0;
    if (!smem_set) {
        cudaFuncSetAttribute(flash_kernel, cudaFuncAttributeMaxDynamicSharedMemorySize,
                             (int)FLASH_SMEM);
        smem_set = 1;
    }
    flash_kernel<<<dim3(S_ / FBQ, H_, B_), FT, FLASH_SMEM>>>(q, k, v, o);

    tf32_gemm_nt<<<ggrid, 256>>>(o, wo, out, BSM, DM_, DM_);
}

// round 7
// speedup vs baseline: 2.2586x; 1.5121x over previous
#include <cuda_runtime.h>
#include <cuda_bf16.h>
#include <math.h>
#include <stdint.h>

#define B_   2
#define S_   2048
#define DM_  2048
#define H_   16
#define DH_  128
#define BSM  (B_ * S_)   // 4096 rows

// ---------------------------------------------------------------------------
// Scratch (static device globals — no allocation allowed)
// ---------------------------------------------------------------------------
__device__ float g_q [(size_t)BSM * DM_];
__device__ float g_k [(size_t)BSM * DM_];
__device__ float g_v [(size_t)BSM * DM_];
__device__ float g_o [(size_t)BSM * DM_];
__device__ __nv_bfloat16 g_xh[(size_t)BSM * DM_];
__device__ __nv_bfloat16 g_xl[(size_t)BSM * DM_];
__device__ __nv_bfloat16 g_oh[(size_t)BSM * DM_];
__device__ __nv_bfloat16 g_ol[(size_t)BSM * DM_];
__device__ __nv_bfloat16 g_wqh[(size_t)DM_ * DM_];
__device__ __nv_bfloat16 g_wql[(size_t)DM_ * DM_];
__device__ __nv_bfloat16 g_wkh[(size_t)DM_ * DM_];
__device__ __nv_bfloat16 g_wkl[(size_t)DM_ * DM_];
__device__ __nv_bfloat16 g_wvh[(size_t)DM_ * DM_];
__device__ __nv_bfloat16 g_wvl[(size_t)DM_ * DM_];
__device__ __nv_bfloat16 g_woh[(size_t)DM_ * DM_];
__device__ __nv_bfloat16 g_wol[(size_t)DM_ * DM_];

// ---------------------------------------------------------------------------
// Helpers
// ---------------------------------------------------------------------------
__device__ __forceinline__ void mma_bf16(float* c, const uint32_t* a, const uint32_t* b) {
    asm volatile(
        "mma.sync.aligned.m16n8k16.row.col.f32.bf16.bf16.f32 "
        "{%0,%1,%2,%3}, {%4,%5,%6,%7}, {%8,%9}, {%0,%1,%2,%3};"
        : "+f"(c[0]), "+f"(c[1]), "+f"(c[2]), "+f"(c[3])
        : "r"(a[0]), "r"(a[1]), "r"(a[2]), "r"(a[3]), "r"(b[0]), "r"(b[1]));
}

__device__ __forceinline__ void cp16(void* smem_dst, const void* gmem_src) {
    uint32_t sa = (uint32_t)__cvta_generic_to_shared(smem_dst);
    asm volatile("cp.async.cg.shared.global [%0], [%1], 16;" :: "r"(sa), "l"(gmem_src));
}
__device__ __forceinline__ void cp_commit() { asm volatile("cp.async.commit_group;"); }
__device__ __forceinline__ void cp_wait1() { asm volatile("cp.async.wait_group 1;"); }
__device__ __forceinline__ void cp_wait0() { asm volatile("cp.async.wait_group 0;"); }

// split x into bf16 hi + bf16 lo
__device__ __forceinline__ void bfsplit1(float x, __nv_bfloat16& h, __nv_bfloat16& l) {
    h = __float2bfloat16_rn(x);
    l = __float2bfloat16_rn(x - __bfloat162float(h));
}
// pack two bf16 (even -> low half) into a word
__device__ __forceinline__ uint32_t packbf(__nv_bfloat16 e, __nv_bfloat16 o) {
    uint32_t lo = __bfloat16_as_ushort(e), hi = __bfloat16_as_ushort(o);
    return lo | (hi << 16);
}

// ---------------------------------------------------------------------------
// Pre-pass: split fp32 array into bf16 hi/lo arrays (4 elems/thread)
// ---------------------------------------------------------------------------
__global__ void bf_split4(const float4* __restrict__ src, uint2* __restrict__ hi,
                          uint2* __restrict__ lo, int n4) {
    int i = blockIdx.x * blockDim.x + threadIdx.x;
    if (i >= n4) return;
    float4 v = src[i];
    __nv_bfloat16 h0, l0, h1, l1, h2, l2, h3, l3;
    bfsplit1(v.x, h0, l0); bfsplit1(v.y, h1, l1);
    bfsplit1(v.z, h2, l2); bfsplit1(v.w, h3, l3);
    hi[i] = make_uint2(packbf(h0, h1), packbf(h2, h3));
    lo[i] = make_uint2(packbf(l0, l1), packbf(l2, l3));
}

// ---------------------------------------------------------------------------
// bf16x3 GEMM: C[M,N] = A[M,K] @ W[N,K]^T with A,B pre-split hi/lo bf16.
// C = Ah*Bh + Ah*Bl + Al*Bh (fp32-class accuracy).
// Block 128x128x32, 8 warps (warp 32x64), 2-stage cp.async double buffer.
// Smem: rows of 16 words (32 bf16) padded to stride 20 (conflict-free frags).
// ---------------------------------------------------------------------------
#define TWB 2560           // words per tile (128 * 20)
#define STAGEW (4 * TWB)   // Ah, Al, Bh, Bl
#define GEMM_SMEM (2 * STAGEW * 4)

__global__ __launch_bounds__(256)
void gemm_bf3(const __nv_bfloat16* __restrict__ Ah, const __nv_bfloat16* __restrict__ Al,
              const __nv_bfloat16* __restrict__ Bh, const __nv_bfloat16* __restrict__ Bl,
              float* __restrict__ C) {
    extern __shared__ uint32_t smw[];

    const int tid  = threadIdx.x;
    const int lane = tid & 31;
    const int w    = tid >> 5;
    const int wm   = w & 3;
    const int wn   = w >> 2;
    const int g    = lane >> 2;
    const int tg   = lane & 3;
    const int rb   = wm * 32;
    const int cb   = wn * 64;
    const int K    = DM_;

    const __nv_bfloat16* gAh = Ah + (size_t)blockIdx.y * 128 * K;
    const __nv_bfloat16* gAl = Al + (size_t)blockIdx.y * 128 * K;
    const __nv_bfloat16* gBh = Bh + (size_t)blockIdx.x * 128 * K;
    const __nv_bfloat16* gBl = Bl + (size_t)blockIdx.x * 128 * K;

    auto issue = [&](int stage, int k0) {
        uint32_t* base = smw + stage * STAGEW;
#pragma unroll
        for (int p = 0; p < 2; p++) {
            int s   = p * 256 + tid;      // 0..511
            int row = s >> 2;
            int kq  = s & 3;
            int d   = row * 20 + kq * 4;
            size_t srcoff = (size_t)row * K + k0 + kq * 8;
            cp16(base + d,           gAh + srcoff);
            cp16(base + TWB + d,     gAl + srcoff);
            cp16(base + 2 * TWB + d, gBh + srcoff);
            cp16(base + 3 * TWB + d, gBl + srcoff);
        }
        cp_commit();
    };

    float acc[2][8][4];
#pragma unroll
    for (int mt = 0; mt < 2; mt++)
#pragma unroll
        for (int nt = 0; nt < 8; nt++)
#pragma unroll
            for (int i = 0; i < 4; i++) acc[mt][nt][i] = 0.f;

    issue(0, 0);
    issue(1, 32);

    const int KT = K / 32;   // 64
    for (int kt = 0; kt < KT; kt++) {
        if (kt == KT - 1) cp_wait0(); else cp_wait1();
        __syncthreads();

        const uint32_t* bAh = smw + (kt & 1) * STAGEW;
        const uint32_t* bAl = bAh + TWB;
        const uint32_t* bBh = bAh + 2 * TWB;
        const uint32_t* bBl = bAh + 3 * TWB;

#pragma unroll
        for (int kc = 0; kc < 2; kc++) {
            const int kb = kc * 8;
            uint32_t ah[2][4], al[2][4];
#pragma unroll
            for (int mt = 0; mt < 2; mt++) {
                int r0 = (rb + mt * 16 + g) * 20;
                int r1 = r0 + 8 * 20;
                ah[mt][0] = bAh[r0 + kb + tg];     ah[mt][1] = bAh[r1 + kb + tg];
                ah[mt][2] = bAh[r0 + kb + 4 + tg]; ah[mt][3] = bAh[r1 + kb + 4 + tg];
                al[mt][0] = bAl[r0 + kb + tg];     al[mt][1] = bAl[r1 + kb + tg];
                al[mt][2] = bAl[r0 + kb + 4 + tg]; al[mt][3] = bAl[r1 + kb + 4 + tg];
            }
#pragma unroll
            for (int nt = 0; nt < 8; nt++) {
                int n = (cb + nt * 8 + g) * 20;
                uint32_t bh[2] = { bBh[n + kb + tg], bBh[n + kb + 4 + tg] };
                uint32_t bl[2] = { bBl[n + kb + tg], bBl[n + kb + 4 + tg] };
#pragma unroll
                for (int mt = 0; mt < 2; mt++) {
                    mma_bf16(acc[mt][nt], ah[mt], bh);
                    mma_bf16(acc[mt][nt], ah[mt], bl);
                    mma_bf16(acc[mt][nt], al[mt], bh);
                }
            }
        }

        if (kt + 2 < KT) {
            __syncthreads();
            issue(kt & 1, (kt + 2) * 32);
        }
    }

#pragma unroll
    for (int mt = 0; mt < 2; mt++)
#pragma unroll
        for (int nt = 0; nt < 8; nt++) {
            int row = blockIdx.y * 128 + rb + mt * 16 + g;
            int col = blockIdx.x * 128 + cb + nt * 8 + tg * 2;
            *(float2*)(C + (size_t)row * DM_ + col) =
                make_float2(acc[mt][nt][0], acc[mt][nt][1]);
            *(float2*)(C + (size_t)(row + 8) * DM_ + col) =
                make_float2(acc[mt][nt][2], acc[mt][nt][3]);
        }
}

// ---------------------------------------------------------------------------
// RMSNorm (head dim 128) + RoPE, one warp per (b,s,h) row, in-place (fp32).
// ---------------------------------------------------------------------------
__global__ __launch_bounds__(256)
void norm_rope(float* __restrict__ t, const float* __restrict__ rope,
               const float* __restrict__ w) {
    int warp = (blockIdx.x * blockDim.x + threadIdx.x) >> 5;
    int lane = threadIdx.x & 31;
    if (warp >= BSM * H_) return;
    int h  = warp % H_;
    int bs = warp / H_;
    int s  = bs % S_;

    float* row = t + (size_t)bs * DM_ + h * DH_;
    float v0 = row[lane], v1 = row[lane + 32], v2 = row[lane + 64], v3 = row[lane + 96];
    float ss = v0 * v0 + v1 * v1 + v2 * v2 + v3 * v3;
#pragma unroll
    for (int o = 16; o; o >>= 1) ss += __shfl_xor_sync(0xFFFFFFFFu, ss, o);
    float inv = rsqrtf(ss * (1.0f / 128.0f) + 1e-6f);
    v0 *= inv * w[lane];      v1 *= inv * w[lane + 32];
    v2 *= inv * w[lane + 64]; v3 *= inv * w[lane + 96];

    const float* f = rope + (size_t)s * 256;
    float f00 = f[lane * 4 + 0], f01 = f[lane * 4 + 1];
    float f10 = f[lane * 4 + 2], f11 = f[lane * 4 + 3];
    float y0 = f00 * v0 + f01 * v2;
    float y2 = f10 * v0 + f11 * v2;
    int i2 = lane + 32;
    float g00 = f[i2 * 4 + 0], g01 = f[i2 * 4 + 1];
    float g10 = f[i2 * 4 + 2], g11 = f[i2 * 4 + 3];
    float y1 = g00 * v1 + g01 * v3;
    float y3 = g10 * v1 + g11 * v3;

    row[lane] = y0; row[lane + 32] = y1; row[lane + 64] = y2; row[lane + 96] = y3;
}

// ---------------------------------------------------------------------------
// bf16x3 flash attention. 512 threads (16 warps), BQ=64, BKV=64.
// All matmuls via m16n8k16 bf16 mma with hi/lo split: hh + hl + lh.
// Smem word strides: Q/K 68, Vt/P 36, scores(f32) 68 — frag LDS conflict-free.
// ---------------------------------------------------------------------------
#define QKW 68
#define VPW 36
#define SFW 68
// words: Qh/Ql 2*4352, Kh/Kl 2*4352, Vth/Vtl 2*4608, Ph/Pl 2*2304, Sf 4352, stats 192
#define OFF_QL  4352
#define OFF_KH  8704
#define OFF_KL  13056
#define OFF_VTH 17408
#define OFF_VTL 22016
#define OFF_PH  26624
#define OFF_PL  28928
#define OFF_SF  31232
#define OFF_ST  35584
#define FLASH_SMEM ((OFF_ST + 192) * 4)

__global__ __launch_bounds__(512, 1)
void flash_bf3(const float* __restrict__ Q, const float* __restrict__ Kg,
               const float* __restrict__ Vg, float* __restrict__ O) {
    extern __shared__ uint32_t smw[];
    uint32_t* Qh  = smw;
    uint32_t* Ql  = smw + OFF_QL;
    uint32_t* Kh  = smw + OFF_KH;
    uint32_t* Kl  = smw + OFF_KL;
    uint32_t* Vth = smw + OFF_VTH;
    uint32_t* Vtl = smw + OFF_VTL;
    uint32_t* Ph  = smw + OFF_PH;
    uint32_t* Pl  = smw + OFF_PL;
    float*    Sf  = (float*)(smw + OFF_SF);
    float*    m_s  = (float*)(smw + OFF_ST);
    float*    l_s  = m_s + 64;
    float*    al_s = l_s + 64;

    const int tid  = threadIdx.x;
    const int lane = tid & 31;
    const int w    = tid >> 5;
    const int g    = lane >> 2;
    const int tg   = lane & 3;
    const int q0   = blockIdx.x * 64;
    const int h    = blockIdx.y;
    const int b    = blockIdx.z;
    const size_t headoff = (size_t)h * DH_;
    const size_t rowbase = (size_t)b * S_;
    const int lr = tid & 63;
    const int lc = tid >> 6;

    // Load Q tile: scale by 1/sqrt(DH), split hi/lo bf16
    {
        const float scale = 0.08838834764831845f;
        const float* qrow = Q + (rowbase + q0 + lr) * (size_t)DM_ + headoff + lc * 16;
#pragma unroll
        for (int i = 0; i < 4; i++) {
            float4 v = *(const float4*)(qrow + i * 4);
            v.x *= scale; v.y *= scale; v.z *= scale; v.w *= scale;
            __nv_bfloat16 h0, l0, h1, l1, h2, l2, h3, l3;
            bfsplit1(v.x, h0, l0); bfsplit1(v.y, h1, l1);
            bfsplit1(v.z, h2, l2); bfsplit1(v.w, h3, l3);
            int widx = lr * QKW + lc * 8 + i * 2;
            Qh[widx]     = packbf(h0, h1); Qh[widx + 1] = packbf(h2, h3);
            Ql[widx]     = packbf(l0, l1); Ql[widx + 1] = packbf(l2, l3);
        }
    }
    if (tid < 64) { m_s[tid] = -1e30f; l_s[tid] = 0.f; }

    const int srb = (w & 3) * 16;   // warp's q-row base
    const int scb = (w >> 2) * 16;  // warp's kv-col base (scores)
    const int ob  = (w >> 2) * 32;  // warp's dh-col base (O)
    const int ra  = srb + g;
    const int ra8 = srb + g + 8;

    float oacc[4][4];
#pragma unroll
    for (int nt = 0; nt < 4; nt++)
#pragma unroll
        for (int i = 0; i < 4; i++) oacc[nt][i] = 0.f;

    for (int j0 = 0; j0 < S_; j0 += 64) {
        // Fill K (split) and V transposed (split)
        {
            const float* krow = Kg + (rowbase + j0 + lr) * (size_t)DM_ + headoff + lc * 16;
#pragma unroll
            for (int i = 0; i < 4; i++) {
                float4 v = *(const float4*)(krow + i * 4);
                __nv_bfloat16 h0, l0, h1, l1, h2, l2, h3, l3;
                bfsplit1(v.x, h0, l0); bfsplit1(v.y, h1, l1);
                bfsplit1(v.z, h2, l2); bfsplit1(v.w, h3, l3);
                int widx = lr * QKW + lc * 8 + i * 2;
                Kh[widx]     = packbf(h0, h1); Kh[widx + 1] = packbf(h2, h3);
                Kl[widx]     = packbf(l0, l1); Kl[widx + 1] = packbf(l2, l3);
            }
            const float* vrow = Vg + (rowbase + j0 + lr) * (size_t)DM_ + headoff + lc * 16;
            __nv_bfloat16* vthb = (__nv_bfloat16*)Vth;
            __nv_bfloat16* vtlb = (__nv_bfloat16*)Vtl;
#pragma unroll
            for (int i = 0; i < 4; i++) {
                float4 v = *(const float4*)(vrow + i * 4);
                int d = lc * 16 + i * 4;
                __nv_bfloat16 hh, ll;
                bfsplit1(v.x, hh, ll);
                vthb[(d + 0) * (2 * VPW) + lr] = hh; vtlb[(d + 0) * (2 * VPW) + lr] = ll;
                bfsplit1(v.y, hh, ll);
                vthb[(d + 1) * (2 * VPW) + lr] = hh; vtlb[(d + 1) * (2 * VPW) + lr] = ll;
                bfsplit1(v.z, hh, ll);
                vthb[(d + 2) * (2 * VPW) + lr] = hh; vtlb[(d + 2) * (2 * VPW) + lr] = ll;
                bfsplit1(v.w, hh, ll);
                vthb[(d + 3) * (2 * VPW) + lr] = hh; vtlb[(d + 3) * (2 * VPW) + lr] = ll;
            }
        }
        __syncthreads();

        // Scores: S = Q @ K^T (bf16x3), each warp 16x16
        {
            float sa[2][4];
#pragma unroll
            for (int nt = 0; nt < 2; nt++)
#pragma unroll
                for (int i = 0; i < 4; i++) sa[nt][i] = 0.f;
#pragma unroll
            for (int c = 0; c < 8; c++) {
                int kb = c * 8;
                uint32_t qh[4] = { Qh[ra * QKW + kb + tg],     Qh[ra8 * QKW + kb + tg],
                                   Qh[ra * QKW + kb + 4 + tg], Qh[ra8 * QKW + kb + 4 + tg] };
                uint32_t ql[4] = { Ql[ra * QKW + kb + tg],     Ql[ra8 * QKW + kb + tg],
                                   Ql[ra * QKW + kb + 4 + tg], Ql[ra8 * QKW + kb + 4 + tg] };
#pragma unroll
                for (int nt = 0; nt < 2; nt++) {
                    int n = (scb + nt * 8 + g) * QKW;
                    uint32_t kh[2] = { Kh[n + kb + tg], Kh[n + kb + 4 + tg] };
                    uint32_t kl[2] = { Kl[n + kb + tg], Kl[n + kb + 4 + tg] };
                    mma_bf16(sa[nt], qh, kh);
                    mma_bf16(sa[nt], qh, kl);
                    mma_bf16(sa[nt], ql, kh);
                }
            }
#pragma unroll
            for (int nt = 0; nt < 2; nt++) {
                int col = scb + nt * 8 + tg * 2;
                *(float2*)&Sf[ra  * SFW + col] = make_float2(sa[nt][0], sa[nt][1]);
                *(float2*)&Sf[ra8 * SFW + col] = make_float2(sa[nt][2], sa[nt][3]);
            }
        }
        __syncthreads();

        // Online softmax: 8 threads/row; write P split hi/lo bf16
        {
            int r  = tid >> 3;
            int c8 = (tid & 7) * 8;
            float* srow = Sf + r * SFW + c8;
            float4 v0 = *(float4*)srow;
            float4 v1 = *(float4*)(srow + 4);
            float mx = fmaxf(fmaxf(fmaxf(v0.x, v0.y), fmaxf(v0.z, v0.w)),
                             fmaxf(fmaxf(v1.x, v1.y), fmaxf(v1.z, v1.w)));
#pragma unroll
            for (int o = 1; o < 8; o <<= 1) mx = fmaxf(mx, __shfl_xor_sync(0xFFFFFFFFu, mx, o));
            float mold = m_s[r];
            mx = fmaxf(mx, mold);
            float p[8];
            p[0] = __expf(v0.x - mx); p[1] = __expf(v0.y - mx);
            p[2] = __expf(v0.z - mx); p[3] = __expf(v0.w - mx);
            p[4] = __expf(v1.x - mx); p[5] = __expf(v1.y - mx);
            p[6] = __expf(v1.z - mx); p[7] = __expf(v1.w - mx);
            __nv_bfloat16 hh[8], ll[8];
            float s = 0.f;
#pragma unroll
            for (int i = 0; i < 8; i++) { bfsplit1(p[i], hh[i], ll[i]); s += p[i]; }
            int wbase = r * VPW + (tid & 7) * 4;
#pragma unroll
            for (int j = 0; j < 4; j++) {
                Ph[wbase + j] = packbf(hh[2 * j], hh[2 * j + 1]);
                Pl[wbase + j] = packbf(ll[2 * j], ll[2 * j + 1]);
            }
#pragma unroll
            for (int o = 1; o < 8; o <<= 1) s += __shfl_xor_sync(0xFFFFFFFFu, s, o);
            if ((tid & 7) == 0) {
                float a = __expf(mold - mx);
                m_s[r]  = mx;
                l_s[r]  = l_s[r] * a + s;
                al_s[r] = a;
            }
        }
        __syncthreads();

        // PV (bf16x3): O = O*alpha + Ph@Vh + Ph@Vl + Pl@Vh
        {
            float a0 = al_s[ra], a1 = al_s[ra8];
#pragma unroll
            for (int nt = 0; nt < 4; nt++) {
                oacc[nt][0] *= a0; oacc[nt][1] *= a0;
                oacc[nt][2] *= a1; oacc[nt][3] *= a1;
            }
#pragma unroll
            for (int c = 0; c < 4; c++) {
                int kb = c * 8;
                uint32_t ph[4] = { Ph[ra * VPW + kb + tg],     Ph[ra8 * VPW + kb + tg],
                                   Ph[ra * VPW + kb + 4 + tg], Ph[ra8 * VPW + kb + 4 + tg] };
                uint32_t pl[4] = { Pl[ra * VPW + kb + tg],     Pl[ra8 * VPW + kb + tg],
                                   Pl[ra * VPW + kb + 4 + tg], Pl[ra8 * VPW + kb + 4 + tg] };
#pragma unroll
                for (int nt = 0; nt < 4; nt++) {
                    int d = (ob + nt * 8 + g) * VPW;
                    uint32_t vh[2] = { Vth[d + kb + tg], Vth[d + kb + 4 + tg] };
                    uint32_t vl[2] = { Vtl[d + kb + tg], Vtl[d + kb + 4 + tg] };
                    mma_bf16(oacc[nt], ph, vh);
                    mma_bf16(oacc[nt], ph, vl);
                    mma_bf16(oacc[nt], pl, vh);
                }
            }
        }
        __syncthreads();
    }

    // Epilogue: normalize by l and store
    {
        float li0 = 1.0f / l_s[ra];
        float li1 = 1.0f / l_s[ra8];
#pragma unroll
        for (int nt = 0; nt < 4; nt++) {
            int col = ob + nt * 8 + tg * 2;
            float* o0 = O + (rowbase + q0 + ra)  * (size_t)DM_ + headoff + col;
            float* o1 = O + (rowbase + q0 + ra8) * (size_t)DM_ + headoff + col;
            *(float2*)o0 = make_float2(oacc[nt][0] * li0, oacc[nt][1] * li0);
            *(float2*)o1 = make_float2(oacc[nt][2] * li1, oacc[nt][3] * li1);
        }
    }
}

// ---------------------------------------------------------------------------
extern "C" void kernel_launch(void* const* d_in, const int* in_sizes, int n_in,
                              void* d_out, int out_size) {
    const float* x    = (const float*)d_in[0];
    const float* rope = (const float*)d_in[1];
    const float* wq   = (const float*)d_in[2];
    const float* wk   = (const float*)d_in[3];
    const float* wv   = (const float*)d_in[4];
    const float* wo   = (const float*)d_in[5];
    const float* qnw  = (const float*)d_in[6];
    const float* knw  = (const float*)d_in[7];
    float* out = (float*)d_out;

    float *q, *k, *v, *o;
    __nv_bfloat16 *xh, *xl, *oh, *ol;
    __nv_bfloat16 *wqh, *wql, *wkh, *wkl, *wvh, *wvl, *woh, *wol;
    cudaGetSymbolAddress((void**)&q,  g_q);
    cudaGetSymbolAddress((void**)&k,  g_k);
    cudaGetSymbolAddress((void**)&v,  g_v);
    cudaGetSymbolAddress((void**)&o,  g_o);
    cudaGetSymbolAddress((void**)&xh, g_xh);
    cudaGetSymbolAddress((void**)&xl, g_xl);
    cudaGetSymbolAddress((void**)&oh, g_oh);
    cudaGetSymbolAddress((void**)&ol, g_ol);
    cudaGetSymbolAddress((void**)&wqh, g_wqh);
    cudaGetSymbolAddress((void**)&wql, g_wql);
    cudaGetSymbolAddress((void**)&wkh, g_wkh);
    cudaGetSymbolAddress((void**)&wkl, g_wkl);
    cudaGetSymbolAddress((void**)&wvh, g_wvh);
    cudaGetSymbolAddress((void**)&wvl, g_wvl);
    cudaGetSymbolAddress((void**)&woh, g_woh);
    cudaGetSymbolAddress((void**)&wol, g_wol);

    static int attr_set = 0;
    if (!attr_set) {
        cudaFuncSetAttribute(gemm_bf3, cudaFuncAttributeMaxDynamicSharedMemorySize,
                             GEMM_SMEM);
        cudaFuncSetAttribute(flash_bf3, cudaFuncAttributeMaxDynamicSharedMemorySize,
                             FLASH_SMEM);
        attr_set = 1;
    }

    const int XN4 = BSM * DM_ / 4;
    const int WN4 = DM_ * DM_ / 4;

    bf_split4<<<(XN4 + 255) / 256, 256>>>((const float4*)x,  (uint2*)xh,  (uint2*)xl,  XN4);
    bf_split4<<<(WN4 + 255) / 256, 256>>>((const float4*)wq, (uint2*)wqh, (uint2*)wql, WN4);
    bf_split4<<<(WN4 + 255) / 256, 256>>>((const float4*)wk, (uint2*)wkh, (uint2*)wkl, WN4);
    bf_split4<<<(WN4 + 255) / 256, 256>>>((const float4*)wv, (uint2*)wvh, (uint2*)wvl, WN4);
    bf_split4<<<(WN4 + 255) / 256, 256>>>((const float4*)wo, (uint2*)woh, (uint2*)wol, WN4);

    dim3 ggrid(DM_ / 128, BSM / 128);   // (16, 32)

    gemm_bf3<<<ggrid, 256, GEMM_SMEM>>>(xh, xl, wqh, wql, q);
    gemm_bf3<<<ggrid, 256, GEMM_SMEM>>>(xh, xl, wkh, wkl, k);
    gemm_bf3<<<ggrid, 256, GEMM_SMEM>>>(xh, xl, wvh, wvl, v);

    int nwarps = BSM * H_;
    norm_rope<<<nwarps / 8, 256>>>(q, rope, qnw);
    norm_rope<<<nwarps / 8, 256>>>(k, rope, knw);

    flash_bf3<<<dim3(S_ / 64, H_, B_), 512, FLASH_SMEM>>>(q, k, v, o);

    bf_split4<<<(XN4 + 255) / 256, 256>>>((const float4*)o, (uint2*)oh, (uint2*)ol, XN4);
    gemm_bf3<<<ggrid, 256, GEMM_SMEM>>>(oh, ol, woh, wol, out);
}

// round 8
// speedup vs baseline: 3.0618x; 1.3556x over previous
#include <cuda_runtime.h>
#include <cuda_bf16.h>
#include <math.h>
#include <stdint.h>

#define B_   2
#define S_   2048
#define DM_  2048
#define H_   16
#define DH_  128
#define BSM  (B_ * S_)   // 4096 rows

// ---------------------------------------------------------------------------
// Scratch (static device globals — no allocation allowed)
// ---------------------------------------------------------------------------
__device__ float g_q [(size_t)BSM * DM_];
__device__ float g_k [(size_t)BSM * DM_];
__device__ __nv_bfloat16 g_xh[(size_t)BSM * DM_];
__device__ __nv_bfloat16 g_xl[(size_t)BSM * DM_];
__device__ __nv_bfloat16 g_qh[(size_t)BSM * DM_];   // [b][h][s][d] pre-scaled
__device__ __nv_bfloat16 g_ql[(size_t)BSM * DM_];
__device__ __nv_bfloat16 g_kh[(size_t)BSM * DM_];   // [b][h][s][d]
__device__ __nv_bfloat16 g_kl[(size_t)BSM * DM_];
__device__ __nv_bfloat16 g_vth[(size_t)BSM * DM_];  // [b][h][d][s] transposed
__device__ __nv_bfloat16 g_vtl[(size_t)BSM * DM_];
__device__ __nv_bfloat16 g_oh[(size_t)BSM * DM_];   // [token][dmodel]
__device__ __nv_bfloat16 g_ol[(size_t)BSM * DM_];
__device__ __nv_bfloat16 g_wqh[(size_t)DM_ * DM_];
__device__ __nv_bfloat16 g_wql[(size_t)DM_ * DM_];
__device__ __nv_bfloat16 g_wkh[(size_t)DM_ * DM_];
__device__ __nv_bfloat16 g_wkl[(size_t)DM_ * DM_];
__device__ __nv_bfloat16 g_wvh[(size_t)DM_ * DM_];
__device__ __nv_bfloat16 g_wvl[(size_t)DM_ * DM_];
__device__ __nv_bfloat16 g_woh[(size_t)DM_ * DM_];
__device__ __nv_bfloat16 g_wol[(size_t)DM_ * DM_];

// ---------------------------------------------------------------------------
// Helpers
// ---------------------------------------------------------------------------
__device__ __forceinline__ void mma_bf16(float* c, const uint32_t* a, const uint32_t* b) {
    asm volatile(
        "mma.sync.aligned.m16n8k16.row.col.f32.bf16.bf16.f32 "
        "{%0,%1,%2,%3}, {%4,%5,%6,%7}, {%8,%9}, {%0,%1,%2,%3};"
        : "+f"(c[0]), "+f"(c[1]), "+f"(c[2]), "+f"(c[3])
        : "r"(a[0]), "r"(a[1]), "r"(a[2]), "r"(a[3]), "r"(b[0]), "r"(b[1]));
}

__device__ __forceinline__ void cp16(void* smem_dst, const void* gmem_src) {
    uint32_t sa = (uint32_t)__cvta_generic_to_shared(smem_dst);
    asm volatile("cp.async.cg.shared.global [%0], [%1], 16;" :: "r"(sa), "l"(gmem_src));
}
__device__ __forceinline__ void cp_commit() { asm volatile("cp.async.commit_group;"); }
__device__ __forceinline__ void cp_wait1() { asm volatile("cp.async.wait_group 1;"); }
__device__ __forceinline__ void cp_wait0() { asm volatile("cp.async.wait_group 0;"); }

__device__ __forceinline__ void bfsplit1(float x, __nv_bfloat16& h, __nv_bfloat16& l) {
    h = __float2bfloat16_rn(x);
    l = __float2bfloat16_rn(x - __bfloat162float(h));
}
__device__ __forceinline__ uint32_t packbf(__nv_bfloat16 e, __nv_bfloat16 o) {
    uint32_t lo = __bfloat16_as_ushort(e), hi = __bfloat16_as_ushort(o);
    return lo | (hi << 16);
}
// pack fp32 pair: hi word + lo word
__device__ __forceinline__ void packsplit2(float a, float b, uint32_t& wh, uint32_t& wl) {
    __nv_bfloat16 ha, la, hb, lb;
    bfsplit1(a, ha, la); bfsplit1(b, hb, lb);
    wh = packbf(ha, hb); wl = packbf(la, lb);
}

// ---------------------------------------------------------------------------
// Pre-pass: split fp32 array into bf16 hi/lo arrays
// ---------------------------------------------------------------------------
__global__ void bf_split4(const float4* __restrict__ src, uint2* __restrict__ hi,
                          uint2* __restrict__ lo, int n4) {
    int i = blockIdx.x * blockDim.x + threadIdx.x;
    if (i >= n4) return;
    float4 v = src[i];
    __nv_bfloat16 h0, l0, h1, l1, h2, l2, h3, l3;
    bfsplit1(v.x, h0, l0); bfsplit1(v.y, h1, l1);
    bfsplit1(v.z, h2, l2); bfsplit1(v.w, h3, l3);
    hi[i] = make_uint2(packbf(h0, h1), packbf(h2, h3));
    lo[i] = make_uint2(packbf(l0, l1), packbf(l2, l3));
}

// ---------------------------------------------------------------------------
// bf16x3 GEMM: C[M,N] = A[M,K] @ W[N,K]^T with A,B pre-split hi/lo bf16.
// OUT=0: fp32 C. OUT=1: V path — store bf16-split TRANSPOSED per head:
//        Th/Tl[((b*16+h)*128+d)*2048 + s].
// ---------------------------------------------------------------------------
#define TWB 2560           // words per tile (128 * 20)
#define STAGEW (4 * TWB)
#define GEMM_SMEM (2 * STAGEW * 4)

template<int OUT>
__global__ __launch_bounds__(256)
void gemm_bf3(const __nv_bfloat16* __restrict__ Ah, const __nv_bfloat16* __restrict__ Al,
              const __nv_bfloat16* __restrict__ Bh, const __nv_bfloat16* __restrict__ Bl,
              float* __restrict__ C,
              __nv_bfloat16* __restrict__ Th, __nv_bfloat16* __restrict__ Tl) {
    extern __shared__ uint32_t smw[];

    const int tid  = threadIdx.x;
    const int lane = tid & 31;
    const int w    = tid >> 5;
    const int wm   = w & 3;
    const int wn   = w >> 2;
    const int g    = lane >> 2;
    const int tg   = lane & 3;
    const int rb   = wm * 32;
    const int cb   = wn * 64;
    const int K    = DM_;

    const __nv_bfloat16* gAh = Ah + (size_t)blockIdx.y * 128 * K;
    const __nv_bfloat16* gAl = Al + (size_t)blockIdx.y * 128 * K;
    const __nv_bfloat16* gBh = Bh + (size_t)blockIdx.x * 128 * K;
    const __nv_bfloat16* gBl = Bl + (size_t)blockIdx.x * 128 * K;

    auto issue = [&](int stage, int k0) {
        uint32_t* base = smw + stage * STAGEW;
#pragma unroll
        for (int p = 0; p < 2; p++) {
            int s   = p * 256 + tid;
            int row = s >> 2;
            int kq  = s & 3;
            int d   = row * 20 + kq * 4;
            size_t srcoff = (size_t)row * K + k0 + kq * 8;
            cp16(base + d,           gAh + srcoff);
            cp16(base + TWB + d,     gAl + srcoff);
            cp16(base + 2 * TWB + d, gBh + srcoff);
            cp16(base + 3 * TWB + d, gBl + srcoff);
        }
        cp_commit();
    };

    float acc[2][8][4];
#pragma unroll
    for (int mt = 0; mt < 2; mt++)
#pragma unroll
        for (int nt = 0; nt < 8; nt++)
#pragma unroll
            for (int i = 0; i < 4; i++) acc[mt][nt][i] = 0.f;

    issue(0, 0);
    issue(1, 32);

    const int KT = K / 32;
    for (int kt = 0; kt < KT; kt++) {
        if (kt == KT - 1) cp_wait0(); else cp_wait1();
        __syncthreads();

        const uint32_t* bAh = smw + (kt & 1) * STAGEW;
        const uint32_t* bAl = bAh + TWB;
        const uint32_t* bBh = bAh + 2 * TWB;
        const uint32_t* bBl = bAh + 3 * TWB;

#pragma unroll
        for (int kc = 0; kc < 2; kc++) {
            const int kb = kc * 8;
            uint32_t ah[2][4], al[2][4];
#pragma unroll
            for (int mt = 0; mt < 2; mt++) {
                int r0 = (rb + mt * 16 + g) * 20;
                int r1 = r0 + 8 * 20;
                ah[mt][0] = bAh[r0 + kb + tg];     ah[mt][1] = bAh[r1 + kb + tg];
                ah[mt][2] = bAh[r0 + kb + 4 + tg]; ah[mt][3] = bAh[r1 + kb + 4 + tg];
                al[mt][0] = bAl[r0 + kb + tg];     al[mt][1] = bAl[r1 + kb + tg];
                al[mt][2] = bAl[r0 + kb + 4 + tg]; al[mt][3] = bAl[r1 + kb + 4 + tg];
            }
#pragma unroll
            for (int nt = 0; nt < 8; nt++) {
                int n = (cb + nt * 8 + g) * 20;
                uint32_t bh[2] = { bBh[n + kb + tg], bBh[n + kb + 4 + tg] };
                uint32_t bl[2] = { bBl[n + kb + tg], bBl[n + kb + 4 + tg] };
#pragma unroll
                for (int mt = 0; mt < 2; mt++) {
                    mma_bf16(acc[mt][nt], ah[mt], bh);
                    mma_bf16(acc[mt][nt], ah[mt], bl);
                    mma_bf16(acc[mt][nt], al[mt], bh);
                }
            }
        }

        if (kt + 2 < KT) {
            __syncthreads();
            issue(kt & 1, (kt + 2) * 32);
        }
    }

#pragma unroll
    for (int mt = 0; mt < 2; mt++)
#pragma unroll
        for (int nt = 0; nt < 8; nt++) {
            int row = blockIdx.y * 128 + rb + mt * 16 + g;
            int col = blockIdx.x * 128 + cb + nt * 8 + tg * 2;
            if (OUT == 0) {
                *(float2*)(C + (size_t)row * DM_ + col) =
                    make_float2(acc[mt][nt][0], acc[mt][nt][1]);
                *(float2*)(C + (size_t)(row + 8) * DM_ + col) =
                    make_float2(acc[mt][nt][2], acc[mt][nt][3]);
            } else {
                int hh = col >> 7, d = col & 127;
#pragma unroll
                for (int rr = 0; rr < 2; rr++) {
                    int r = row + rr * 8;
                    int bb = r >> 11, s = r & 2047;
                    size_t base = ((size_t)(bb * 16 + hh) * 128 + d) * 2048 + s;
                    float c0 = acc[mt][nt][rr * 2], c1 = acc[mt][nt][rr * 2 + 1];
                    __nv_bfloat16 h0, l0, h1, l1;
                    bfsplit1(c0, h0, l0); bfsplit1(c1, h1, l1);
                    Th[base] = h0;        Tl[base] = l0;
                    Th[base + 2048] = h1; Tl[base + 2048] = l1;
                }
            }
        }
}

// ---------------------------------------------------------------------------
// RMSNorm + RoPE + bf16 split. One warp per (b,s,h) row.
// Reads fp32 [token][dmodel], writes bf16 hi/lo to [b][h][s][d] (scaled).
// Lane owns d = 4*lane .. 4*lane+3.
// ---------------------------------------------------------------------------
__global__ __launch_bounds__(256)
void norm_rope_split(const float* __restrict__ t, const float* __restrict__ rope,
                     const float* __restrict__ w, __nv_bfloat16* __restrict__ outh,
                     __nv_bfloat16* __restrict__ outl, float scale) {
    int warp = (blockIdx.x * blockDim.x + threadIdx.x) >> 5;
    int lane = threadIdx.x & 31;
    if (warp >= BSM * H_) return;
    int h  = warp % H_;
    int bs = warp / H_;          // b*S + s
    int s  = bs % S_;
    int b  = bs / S_;

    const float* row = t + (size_t)bs * DM_ + h * DH_;
    float4 v4 = *(const float4*)(row + 4 * lane);
    float v[4] = { v4.x, v4.y, v4.z, v4.w };

    float ss = v[0] * v[0] + v[1] * v[1] + v[2] * v[2] + v[3] * v[3];
#pragma unroll
    for (int o = 16; o; o >>= 1) ss += __shfl_xor_sync(0xFFFFFFFFu, ss, o);
    float inv = rsqrtf(ss * (1.0f / 128.0f) + 1e-6f);
    const float4 w4 = *(const float4*)(w + 4 * lane);
    v[0] *= inv * w4.x; v[1] *= inv * w4.y; v[2] *= inv * w4.z; v[3] *= inv * w4.w;

    // partner values (d +/- 64)
    float pv[4];
#pragma unroll
    for (int j = 0; j < 4; j++) pv[j] = __shfl_xor_sync(0xFFFFFFFFu, v[j], 16);

    const float* f = rope + (size_t)s * 256;
    float y[4];
#pragma unroll
    for (int j = 0; j < 4; j++) {
        int d = 4 * lane + j;
        int i = d & 63;
        float a, bb;
        if (lane < 16) { a = f[i * 4 + 0]; bb = f[i * 4 + 1]; y[j] = a * v[j] + bb * pv[j]; }
        else           { a = f[i * 4 + 2]; bb = f[i * 4 + 3]; y[j] = a * pv[j] + bb * v[j]; }
        y[j] *= scale;
    }

    __nv_bfloat16 hh[4], ll[4];
#pragma unroll
    for (int j = 0; j < 4; j++) bfsplit1(y[j], hh[j], ll[j]);

    size_t base = ((size_t)(b * H_ + h) * S_ + s) * DH_ + 4 * lane;
    *(uint2*)(outh + base) = make_uint2(packbf(hh[0], hh[1]), packbf(hh[2], hh[3]));
    *(uint2*)(outl + base) = make_uint2(packbf(ll[0], ll[1]), packbf(ll[2], ll[3]));
}

// ---------------------------------------------------------------------------
// Register-resident bf16x3 flash attention.
// 256 threads / 8 warps, BQ=128 (warp w owns q-rows 16w..16w+15), BKV=64.
// Q/K/V pre-split bf16 in gmem; K/V tiles double-buffered via cp.async.
// Scores + P + stats live entirely in registers. O written bf16-split.
// ---------------------------------------------------------------------------
#define FQW 68                         // Q/K row stride (words)
#define FVW 36                         // Vt row stride (words)
#define QWORDS (128 * FQW)             // 8704
#define KTILEW (64 * FQW)              // 4352
#define VTILEW (128 * FVW)             // 4608
#define STG2W  (2 * KTILEW + 2 * VTILEW)  // 17920
#define OFF_STG (2 * QWORDS)           // 17408
#define FLASH_SMEM ((OFF_STG + 2 * STG2W) * 4)   // 212992 B

__global__ __launch_bounds__(256, 1)
void flash_reg(const __nv_bfloat16* __restrict__ Qh, const __nv_bfloat16* __restrict__ Ql,
               const __nv_bfloat16* __restrict__ Kh, const __nv_bfloat16* __restrict__ Kl,
               const __nv_bfloat16* __restrict__ Vth, const __nv_bfloat16* __restrict__ Vtl,
               __nv_bfloat16* __restrict__ Oh, __nv_bfloat16* __restrict__ Ol) {
    extern __shared__ uint32_t smw[];

    const int tid  = threadIdx.x;
    const int lane = tid & 31;
    const int w    = tid >> 5;      // 0..7
    const int g    = lane >> 2;
    const int tg   = lane & 3;
    const int q0   = blockIdx.x * 128;
    const int h    = blockIdx.y;
    const int b    = blockIdx.z;
    const int rw   = w * 16;        // warp q-row base

    const size_t headQ = ((size_t)(b * H_ + h) * S_) * DH_;   // [s][d] layout base
    const __nv_bfloat16* gQh = Qh + headQ + (size_t)q0 * DH_;
    const __nv_bfloat16* gQl = Ql + headQ + (size_t)q0 * DH_;
    const __nv_bfloat16* gKh = Kh + headQ;
    const __nv_bfloat16* gKl = Kl + headQ;
    const size_t headV = ((size_t)(b * H_ + h) * DH_) * S_;   // [d][s] layout base
    const __nv_bfloat16* gVth = Vth + headV;
    const __nv_bfloat16* gVtl = Vtl + headV;

    // Q load (one cp group)
    {
#pragma unroll
        for (int p = 0; p < 16; p++) {
            int t   = p * 256 + tid;
            int reg = t >> 11;            // 0=h, 1=l (uniform per p)
            int idx = t & 2047;
            int row = idx >> 4, ch = idx & 15;
            const __nv_bfloat16* src = (reg ? gQl : gQh) + (size_t)row * DH_ + ch * 8;
            cp16(smw + reg * QWORDS + row * FQW + ch * 4, src);
        }
        cp_commit();
    }

    auto issue_kv = [&](int stage, int j0) {
        uint32_t* base = smw + OFF_STG + stage * STG2W;
#pragma unroll
        for (int p = 0; p < 16; p++) {
            int t   = p * 256 + tid;
            int reg = t >> 10;            // 0:Kh 1:Kl 2:Vth 3:Vtl (uniform per p)
            int idx = t & 1023;
            if (reg < 2) {
                int row = idx >> 4, ch = idx & 15;
                const __nv_bfloat16* src = (reg ? gKl : gKh) + (size_t)(j0 + row) * DH_ + ch * 8;
                cp16(base + reg * KTILEW + row * FQW + ch * 4, src);
            } else {
                int d = idx >> 3, ch = idx & 7;
                const __nv_bfloat16* src = (reg == 3 ? gVtl : gVth) + (size_t)d * S_ + j0 + ch * 8;
                cp16(base + 2 * KTILEW + (reg - 2) * VTILEW + d * FVW + ch * 4, src);
            }
        }
        cp_commit();
    };

    issue_kv(0, 0);
    issue_kv(1, 64);

    float oacc[16][4];
#pragma unroll
    for (int nt = 0; nt < 16; nt++)
#pragma unroll
        for (int i = 0; i < 4; i++) oacc[nt][i] = 0.f;
    float m0 = -1e30f, m1 = -1e30f, l0 = 0.f, l1 = 0.f;

    const int NKT = S_ / 64;   // 32
    for (int kt = 0; kt < NKT; kt++) {
        if (kt == NKT - 1) cp_wait0(); else cp_wait1();
        __syncthreads();

        const uint32_t* Ksh = smw + OFF_STG + (kt & 1) * STG2W;
        const uint32_t* Ksl = Ksh + KTILEW;
        const uint32_t* Vsh = Ksh + 2 * KTILEW;
        const uint32_t* Vsl = Vsh + VTILEW;

        // ---- scores: 16 q-rows x 64 kv per warp, bf16x3 ----
        float sc[8][4];
#pragma unroll
        for (int nt = 0; nt < 8; nt++)
#pragma unroll
            for (int i = 0; i < 4; i++) sc[nt][i] = 0.f;

#pragma unroll
        for (int c = 0; c < 8; c++) {
            int q0w = (rw + g) * FQW + c * 8 + tg;
            int q1w = q0w + 8 * FQW;
            uint32_t ah[4] = { smw[q0w], smw[q1w], smw[q0w + 4], smw[q1w + 4] };
            uint32_t al[4] = { smw[QWORDS + q0w], smw[QWORDS + q1w],
                               smw[QWORDS + q0w + 4], smw[QWORDS + q1w + 4] };
#pragma unroll
            for (int nt = 0; nt < 8; nt++) {
                int n = (nt * 8 + g) * FQW + c * 8 + tg;
                uint32_t kh[2] = { Ksh[n], Ksh[n + 4] };
                uint32_t kl[2] = { Ksl[n], Ksl[n + 4] };
                mma_bf16(sc[nt], ah, kh);
                mma_bf16(sc[nt], ah, kl);
                mma_bf16(sc[nt], al, kh);
            }
        }

        // ---- online softmax in registers (rows rw+g, rw+8+g) ----
        {
            float mx0 = sc[0][0], mx1 = sc[0][2];
#pragma unroll
            for (int j = 0; j < 8; j++) {
                mx0 = fmaxf(mx0, fmaxf(sc[j][0], sc[j][1]));
                mx1 = fmaxf(mx1, fmaxf(sc[j][2], sc[j][3]));
            }
            mx0 = fmaxf(mx0, __shfl_xor_sync(0xFFFFFFFFu, mx0, 1));
            mx0 = fmaxf(mx0, __shfl_xor_sync(0xFFFFFFFFu, mx0, 2));
            mx1 = fmaxf(mx1, __shfl_xor_sync(0xFFFFFFFFu, mx1, 1));
            mx1 = fmaxf(mx1, __shfl_xor_sync(0xFFFFFFFFu, mx1, 2));
            float nm0 = fmaxf(m0, mx0), nm1 = fmaxf(m1, mx1);
            float a0 = __expf(m0 - nm0), a1 = __expf(m1 - nm1);
            m0 = nm0; m1 = nm1;
            float s0 = 0.f, s1 = 0.f;
#pragma unroll
            for (int j = 0; j < 8; j++) {
                sc[j][0] = __expf(sc[j][0] - m0); sc[j][1] = __expf(sc[j][1] - m0);
                sc[j][2] = __expf(sc[j][2] - m1); sc[j][3] = __expf(sc[j][3] - m1);
                s0 += sc[j][0] + sc[j][1];
                s1 += sc[j][2] + sc[j][3];
            }
            s0 += __shfl_xor_sync(0xFFFFFFFFu, s0, 1);
            s0 += __shfl_xor_sync(0xFFFFFFFFu, s0, 2);
            s1 += __shfl_xor_sync(0xFFFFFFFFu, s1, 1);
            s1 += __shfl_xor_sync(0xFFFFFFFFu, s1, 2);
            l0 = l0 * a0 + s0;
            l1 = l1 * a1 + s1;
#pragma unroll
            for (int nt = 0; nt < 16; nt++) {
                oacc[nt][0] *= a0; oacc[nt][1] *= a0;
                oacc[nt][2] *= a1; oacc[nt][3] *= a1;
            }
        }

        // ---- PV: P (registers, split) @ V (smem), bf16x3 ----
#pragma unroll
        for (int c = 0; c < 4; c++) {
            uint32_t ah[4], al[4];
            packsplit2(sc[2 * c][0],     sc[2 * c][1],     ah[0], al[0]);
            packsplit2(sc[2 * c][2],     sc[2 * c][3],     ah[1], al[1]);
            packsplit2(sc[2 * c + 1][0], sc[2 * c + 1][1], ah[2], al[2]);
            packsplit2(sc[2 * c + 1][2], sc[2 * c + 1][3], ah[3], al[3]);
#pragma unroll
            for (int nt = 0; nt < 16; nt++) {
                int n = (nt * 8 + g) * FVW + c * 8 + tg;
                uint32_t vh[2] = { Vsh[n], Vsh[n + 4] };
                uint32_t vl[2] = { Vsl[n], Vsl[n + 4] };
                mma_bf16(oacc[nt], ah, vh);
                mma_bf16(oacc[nt], ah, vl);
                mma_bf16(oacc[nt], al, vh);
            }
        }

        if (kt + 2 < NKT) {
            __syncthreads();
            issue_kv(kt & 1, (kt + 2) * 64);
        }
    }

    // ---- epilogue: normalize, split, store bf16 hi/lo [token][dmodel] ----
    {
        float li0 = 1.0f / l0, li1 = 1.0f / l1;
        size_t tok0 = (size_t)(b * S_ + q0 + rw + g) * DM_ + h * DH_;
        size_t tok1 = tok0 + 8 * DM_;
#pragma unroll
        for (int nt = 0; nt < 16; nt++) {
            int col = nt * 8 + tg * 2;
            uint32_t wh, wl;
            packsplit2(oacc[nt][0] * li0, oacc[nt][1] * li0, wh, wl);
            *(uint32_t*)(Oh + tok0 + col) = wh;
            *(uint32_t*)(Ol + tok0 + col) = wl;
            packsplit2(oacc[nt][2] * li1, oacc[nt][3] * li1, wh, wl);
            *(uint32_t*)(Oh + tok1 + col) = wh;
            *(uint32_t*)(Ol + tok1 + col) = wl;
        }
    }
}

// ---------------------------------------------------------------------------
extern "C" void kernel_launch(void* const* d_in, const int* in_sizes, int n_in,
                              void* d_out, int out_size) {
    const float* x    = (const float*)d_in[0];
    const float* rope = (const float*)d_in[1];
    const float* wq   = (const float*)d_in[2];
    const float* wk   = (const float*)d_in[3];
    const float* wv   = (const float*)d_in[4];
    const float* wo   = (const float*)d_in[5];
    const float* qnw  = (const float*)d_in[6];
    const float* knw  = (const float*)d_in[7];
    float* out = (float*)d_out;

    float *q, *k;
    __nv_bfloat16 *xh, *xl, *qh, *ql, *kh, *kl, *vth, *vtl, *oh, *ol;
    __nv_bfloat16 *wqh, *wql, *wkh, *wkl, *wvh, *wvl, *woh, *wol;
    cudaGetSymbolAddress((void**)&q,   g_q);
    cudaGetSymbolAddress((void**)&k,   g_k);
    cudaGetSymbolAddress((void**)&xh,  g_xh);
    cudaGetSymbolAddress((void**)&xl,  g_xl);
    cudaGetSymbolAddress((void**)&qh,  g_qh);
    cudaGetSymbolAddress((void**)&ql,  g_ql);
    cudaGetSymbolAddress((void**)&kh,  g_kh);
    cudaGetSymbolAddress((void**)&kl,  g_kl);
    cudaGetSymbolAddress((void**)&vth, g_vth);
    cudaGetSymbolAddress((void**)&vtl, g_vtl);
    cudaGetSymbolAddress((void**)&oh,  g_oh);
    cudaGetSymbolAddress((void**)&ol,  g_ol);
    cudaGetSymbolAddress((void**)&wqh, g_wqh);
    cudaGetSymbolAddress((void**)&wql, g_wql);
    cudaGetSymbolAddress((void**)&wkh, g_wkh);
    cudaGetSymbolAddress((void**)&wkl, g_wkl);
    cudaGetSymbolAddress((void**)&wvh, g_wvh);
    cudaGetSymbolAddress((void**)&wvl, g_wvl);
    cudaGetSymbolAddress((void**)&woh, g_woh);
    cudaGetSymbolAddress((void**)&wol, g_wol);

    static int attr_set = 0;
    if (!attr_set) {
        cudaFuncSetAttribute(gemm_bf3<0>, cudaFuncAttributeMaxDynamicSharedMemorySize, GEMM_SMEM);
        cudaFuncSetAttribute(gemm_bf3<1>, cudaFuncAttributeMaxDynamicSharedMemorySize, GEMM_SMEM);
        cudaFuncSetAttribute(flash_reg, cudaFuncAttributeMaxDynamicSharedMemorySize, FLASH_SMEM);
        attr_set = 1;
    }

    const int XN4 = BSM * DM_ / 4;
    const int WN4 = DM_ * DM_ / 4;

    bf_split4<<<(XN4 + 255) / 256, 256>>>((const float4*)x,  (uint2*)xh,  (uint2*)xl,  XN4);
    bf_split4<<<(WN4 + 255) / 256, 256>>>((const float4*)wq, (uint2*)wqh, (uint2*)wql, WN4);
    bf_split4<<<(WN4 + 255) / 256, 256>>>((const float4*)wk, (uint2*)wkh, (uint2*)wkl, WN4);
    bf_split4<<<(WN4 + 255) / 256, 256>>>((const float4*)wv, (uint2*)wvh, (uint2*)wvl, WN4);
    bf_split4<<<(WN4 + 255) / 256, 256>>>((const float4*)wo, (uint2*)woh, (uint2*)wol, WN4);

    dim3 ggrid(DM_ / 128, BSM / 128);   // (16, 32)

    gemm_bf3<0><<<ggrid, 256, GEMM_SMEM>>>(xh, xl, wqh, wql, q, nullptr, nullptr);
    gemm_bf3<0><<<ggrid, 256, GEMM_SMEM>>>(xh, xl, wkh, wkl, k, nullptr, nullptr);
    gemm_bf3<1><<<ggrid, 256, GEMM_SMEM>>>(xh, xl, wvh, wvl, nullptr, vth, vtl);

    int nblocks = (BSM * H_) / 8;   // 8 warps per 256-thread block
    norm_rope_split<<<nblocks, 256>>>(q, rope, qnw, qh, ql, 0.08838834764831845f);
    norm_rope_split<<<nblocks, 256>>>(k, rope, knw, kh, kl, 1.0f);

    flash_reg<<<dim3(S_ / 128, H_, B_), 256, FLASH_SMEM>>>(qh, ql, kh, kl, vth, vtl, oh, ol);

    gemm_bf3<0><<<ggrid, 256, GEMM_SMEM>>>(oh, ol, woh, wol, out, nullptr, nullptr);
}